// round 1
// baseline (speedup 1.0000x reference)
#include <cuda_runtime.h>
#include <cuda_bf16.h>
#include <cstdint>
#include <cmath>

// Problem dims (fixed by the dataset)
#define BB 8
#define TT 2040
#define HH 1536
#define NHD 8
#define HD 192
#define CHUNK 12
#define PAST 12
#define CTXS 24     // CHUNK + PAST
#define FSPAN 13
#define UU (TT / CHUNK)   // 170
#define BT (BB * TT)      // 16320

// Scratch (device globals; no allocation allowed)
__device__ float g_q[(size_t)BT * HH];
__device__ float g_k[(size_t)BT * HH];
__device__ float g_v[(size_t)BT * HH];
__device__ float g_sinproj[FSPAN * HH];
__device__ float g_colscale[HH];

// ---------------------------------------------------------------------------
// colscale[col] = (1/sqrt(HD)) * (1/ln2) * softplus(per_dim_scale[col % HD])
// ---------------------------------------------------------------------------
__global__ void colscale_kernel(const float* __restrict__ ps) {
    int c = blockIdx.x * 256 + threadIdx.x;
    if (c < HH) {
        const float q_scale = 0.104117546f; // 192^-0.5 / ln(2)
        float x = ps[c % HD];
        g_colscale[c] = q_scale * log1pf(expf(x));
    }
}

// ---------------------------------------------------------------------------
// sinproj[f, col] = sum_t pe[f, t] * Wpos[t, col]
// pe[f, t<768]  = sin(pos_f * inv_ts[t]),  pe[f, t>=768] = cos(pos_f * inv_ts[t-768])
// pos_f = PAST - f
// ---------------------------------------------------------------------------
__global__ void sinproj_kernel(const float* __restrict__ Wpos) {
    __shared__ float pe[HH];
    int f = blockIdx.x;
    int col = blockIdx.y * 128 + threadIdx.x;
    float pos = (float)(PAST - f);
    const float log_inc = 9.210340372f / 767.0f;  // ln(10000)/(H/2 - 1)
    for (int t = threadIdx.x; t < HH / 2; t += 128) {
        float it = expf(-log_inc * (float)t);
        float a = pos * it;
        pe[t]            = sinf(a);
        pe[t + HH / 2]   = cosf(a);
    }
    __syncthreads();
    float acc = 0.f;
    for (int t = 0; t < HH; t++)
        acc = fmaf(pe[t], Wpos[(size_t)t * HH + col], acc);
    g_sinproj[f * HH + col] = acc;
}

// ---------------------------------------------------------------------------
// Fused QKV GEMM: C = A(M,K) @ B(K,N); blockIdx.z selects Wq/Wk/Wv -> q/k/v.
// 128x128x16 tiles, 256 threads, 8x8 per thread. Q output scaled by colscale.
// ---------------------------------------------------------------------------
#define BM 128
#define BN 128
#define BKK 16
#define TM 8
#define TN 8

__global__ void __launch_bounds__(256) qkv_gemm(
    const float* __restrict__ A,
    const float* __restrict__ Wq, const float* __restrict__ Wk, const float* __restrict__ Wv)
{
    const int M = BT, N = HH, K = HH;
    const float* Bm;
    float* C;
    bool doscale = false;
    if (blockIdx.z == 0)      { Bm = Wq; C = g_q; doscale = true; }
    else if (blockIdx.z == 1) { Bm = Wk; C = g_k; }
    else                      { Bm = Wv; C = g_v; }

    __shared__ float As[BKK][BM + 4];
    __shared__ float Bs[BKK][BN];

    int tid = threadIdx.x;
    int tx = tid & 15, ty = tid >> 4;
    int row0 = blockIdx.y * BM;
    int col0 = blockIdx.x * BN;

    float acc[TM][TN];
    #pragma unroll
    for (int i = 0; i < TM; i++)
        #pragma unroll
        for (int j = 0; j < TN; j++) acc[i][j] = 0.f;

    for (int kt = 0; kt < K; kt += BKK) {
        // A tile: 128 rows x 16 cols (transposed into As)
        #pragma unroll
        for (int it = 0; it < 2; it++) {
            int id = tid + it * 256;
            int r = id >> 2;
            int c4 = (id & 3) * 4;
            float4 va = make_float4(0.f, 0.f, 0.f, 0.f);
            if (row0 + r < M)
                va = *(const float4*)&A[(size_t)(row0 + r) * K + kt + c4];
            As[c4 + 0][r] = va.x;
            As[c4 + 1][r] = va.y;
            As[c4 + 2][r] = va.z;
            As[c4 + 3][r] = va.w;
        }
        // B tile: 16 rows x 128 cols
        #pragma unroll
        for (int it = 0; it < 2; it++) {
            int id = tid + it * 256;
            int r = id >> 5;
            int c4 = (id & 31) * 4;
            *(float4*)&Bs[r][c4] = *(const float4*)&Bm[(size_t)(kt + r) * N + col0 + c4];
        }
        __syncthreads();

        #pragma unroll
        for (int kk = 0; kk < BKK; kk++) {
            float ar[TM], br[TN];
            #pragma unroll
            for (int i = 0; i < TM; i++) ar[i] = As[kk][ty * TM + i];
            #pragma unroll
            for (int j = 0; j < TN; j++) br[j] = Bs[kk][tx * TN + j];
            #pragma unroll
            for (int i = 0; i < TM; i++)
                #pragma unroll
                for (int j = 0; j < TN; j++)
                    acc[i][j] = fmaf(ar[i], br[j], acc[i][j]);
        }
        __syncthreads();
    }

    #pragma unroll
    for (int i = 0; i < TM; i++) {
        int r = row0 + ty * TM + i;
        if (r >= M) continue;
        #pragma unroll
        for (int j = 0; j < TN; j += 4) {
            int c = col0 + tx * TN + j;
            float4 o;
            o.x = acc[i][j]; o.y = acc[i][j + 1]; o.z = acc[i][j + 2]; o.w = acc[i][j + 3];
            if (doscale) {
                o.x *= g_colscale[c];     o.y *= g_colscale[c + 1];
                o.z *= g_colscale[c + 2]; o.w *= g_colscale[c + 3];
            }
            *(float4*)&C[(size_t)r * N + c] = o;
        }
    }
}

// ---------------------------------------------------------------------------
// Attention: one block per (u, n, b). 288 threads.
// logits[w,c] = tanh((q[w].k[c] + q[w].sinproj[c-w]) / 50) * 50 on the band
// 0 <= c-w <= 12 (masked elsewhere), softmax over c, then probs @ v.
// ---------------------------------------------------------------------------
#define NTHR 288
#define PADR 200

__global__ void __launch_bounds__(NTHR) attn_kernel(
    const unsigned char* __restrict__ mask, float* __restrict__ out)
{
    int u = blockIdx.x, n = blockIdx.y, b = blockIdx.z;
    int tid = threadIdx.x;

    __shared__ float sq[CHUNK][PADR];
    __shared__ float skv[CTXS][PADR];
    __shared__ float sp[FSPAN][PADR];
    __shared__ float sbd[CHUNK][16];
    __shared__ float sprob[CHUNK][CTXS];
    __shared__ unsigned char svalid[CTXS];

    const size_t headoff = (size_t)n * HD;
    const size_t qbase = ((size_t)b * TT + (size_t)u * CHUNK) * HH + headoff;

    // load q tile (12 x 192)
    for (int i = tid; i < CHUNK * HD; i += NTHR) {
        int w = i / HD, d = i % HD;
        sq[w][d] = g_q[qbase + (size_t)w * HH + d];
    }
    // load k context (24 x 192), zero-padded at sequence start
    for (int i = tid; i < CTXS * HD; i += NTHR) {
        int c = i / HD, d = i % HD;
        int pos = u * CHUNK + c - PAST;
        float val = 0.f;
        if (pos >= 0 && pos < TT)
            val = g_k[((size_t)b * TT + pos) * HH + headoff + d];
        skv[c][d] = val;
    }
    // load sinproj for this head (13 x 192)
    for (int i = tid; i < FSPAN * HD; i += NTHR) {
        int f = i / HD, d = i % HD;
        sp[f][d] = g_sinproj[f * HH + headoff + d];
    }
    if (tid < CTXS) {
        int pos = u * CHUNK + tid - PAST;
        svalid[tid] = (pos >= 0 && pos < TT) ? (mask[(size_t)b * TT + pos] ? 0 : 1) : 0;
    }
    __syncthreads();

    // term_bd[w][f] = q[w] . sinproj[f]
    for (int i = tid; i < CHUNK * FSPAN; i += NTHR) {
        int w = i / FSPAN, f = i % FSPAN;
        float acc = 0.f;
        #pragma unroll 8
        for (int d = 0; d < HD; d++) acc = fmaf(sq[w][d], sp[f][d], acc);
        sbd[w][f] = acc;
    }
    __syncthreads();

    // logits (12 x 24): one thread each
    {
        int w = tid / CTXS, c = tid % CTXS;  // tid < 288 == 12*24
        float acc = 0.f;
        #pragma unroll 8
        for (int d = 0; d < HD; d++) acc = fmaf(sq[w][d], skv[c][d], acc);
        int f = c - w;
        bool band = (f >= 0 && f <= PAST);
        if (band) acc += sbd[w][f];
        acc = tanhf(acc * 0.02f) * 50.f;
        bool ok = band && svalid[c];
        sprob[w][c] = ok ? acc : -1e30f;
    }
    __syncthreads();

    // row softmax (12 rows of 24)
    if (tid < CHUNK) {
        float m = -1e30f;
        #pragma unroll
        for (int c = 0; c < CTXS; c++) m = fmaxf(m, sprob[tid][c]);
        float e[CTXS];
        float s = 0.f;
        #pragma unroll
        for (int c = 0; c < CTXS; c++) { e[c] = __expf(sprob[tid][c] - m); s += e[c]; }
        float inv = 1.f / s;
        #pragma unroll
        for (int c = 0; c < CTXS; c++) sprob[tid][c] = e[c] * inv;
    }
    __syncthreads();

    // reload skv with V
    for (int i = tid; i < CTXS * HD; i += NTHR) {
        int c = i / HD, d = i % HD;
        int pos = u * CHUNK + c - PAST;
        float val = 0.f;
        if (pos >= 0 && pos < TT)
            val = g_v[((size_t)b * TT + pos) * HH + headoff + d];
        skv[c][d] = val;
    }
    __syncthreads();

    // out[w][d] = sum_c probs[w][c] * v[c][d]
    for (int i = tid; i < CHUNK * HD; i += NTHR) {
        int w = i / HD, d = i % HD;
        float acc = 0.f;
        #pragma unroll
        for (int c = 0; c < CTXS; c++) acc = fmaf(sprob[w][c], skv[c][d], acc);
        out[qbase + (size_t)w * HH + d] = acc;
    }
}

// ---------------------------------------------------------------------------
extern "C" void kernel_launch(void* const* d_in, const int* in_sizes, int n_in,
                              void* d_out, int out_size) {
    const float* hs   = (const float*)d_in[0];
    const float* Wq   = (const float*)d_in[1];
    const float* Wk   = (const float*)d_in[2];
    const float* Wv   = (const float*)d_in[3];
    const float* Wpos = (const float*)d_in[4];
    const float* ps   = (const float*)d_in[5];
    const unsigned char* mask = (const unsigned char*)d_in[6];
    float* out = (float*)d_out;

    colscale_kernel<<<(HH + 255) / 256, 256>>>(ps);
    sinproj_kernel<<<dim3(FSPAN, HH / 128), 128>>>(Wpos);

    dim3 ggrid(HH / BN, (BT + BM - 1) / BM, 3);
    qkv_gemm<<<ggrid, 256>>>(hs, Wq, Wk, Wv);

    attn_kernel<<<dim3(UU, NHD, BB), NTHR>>>(mask, out);
}

// round 3
// speedup vs baseline: 1.4832x; 1.4832x over previous
#include <cuda_runtime.h>
#include <cuda_bf16.h>
#include <cstdint>
#include <cmath>

// Problem dims (fixed by the dataset)
#define BB 8
#define TT 2040
#define HH 1536
#define NHD 8
#define HD 192
#define CHUNK 12
#define PAST 12
#define CTXS 24     // CHUNK + PAST
#define FSPAN 13
#define UU (TT / CHUNK)   // 170
#define BT (BB * TT)      // 16320

// Scratch (device globals; no allocation allowed)
__device__ float g_q[(size_t)BT * HH];
__device__ float g_k[(size_t)BT * HH];
__device__ float g_v[(size_t)BT * HH];
__device__ float g_sinproj[FSPAN * HH];
__device__ float g_colscale[HH];

// ---------------------------------------------------------------------------
// colscale[col] = (1/sqrt(HD)) * (1/ln2) * softplus(per_dim_scale[col % HD])
// ---------------------------------------------------------------------------
__global__ void colscale_kernel(const float* __restrict__ ps) {
    int c = blockIdx.x * 256 + threadIdx.x;
    if (c < HH) {
        const float q_scale = 0.104117546f; // 192^-0.5 / ln(2)
        float x = ps[c % HD];
        g_colscale[c] = q_scale * log1pf(expf(x));
    }
}

// ---------------------------------------------------------------------------
// sinproj[f, col] = sum_t pe[f, t] * Wpos[t, col]
// ---------------------------------------------------------------------------
__global__ void sinproj_kernel(const float* __restrict__ Wpos) {
    __shared__ float pe[HH];
    int f = blockIdx.x;
    int col = blockIdx.y * 128 + threadIdx.x;
    float pos = (float)(PAST - f);
    const float log_inc = 9.210340372f / 767.0f;  // ln(10000)/(H/2 - 1)
    for (int t = threadIdx.x; t < HH / 2; t += 128) {
        float it = expf(-log_inc * (float)t);
        float a = pos * it;
        pe[t]            = sinf(a);
        pe[t + HH / 2]   = cosf(a);
    }
    __syncthreads();
    float acc = 0.f;
    for (int t = 0; t < HH; t++)
        acc = fmaf(pe[t], Wpos[(size_t)t * HH + col], acc);
    g_sinproj[f * HH + col] = acc;
}

// ---------------------------------------------------------------------------
// Tensor-core QKV GEMM with bf16 hi/lo split (3-MMA emulated fp32).
// C = A(M,K) @ B(K,N); blockIdx.z selects Wq/Wk/Wv -> q/k/v.
// Block tile 128x128, K-tile 32. 8 warps (2x4), warp tile 64x32.
// Q path: colscale folded into B (Wq column scaling) at load time.
// ---------------------------------------------------------------------------
#define BM 128
#define BN 128
#define KT 32
#define ASTR 40     // As row stride in bf16 (conflict-free ldmatrix)
#define BSTR 136    // Bs row stride in bf16

__device__ __forceinline__ void mma_bf16(float* c, const uint32_t* a, const uint32_t* b) {
    asm volatile(
        "mma.sync.aligned.m16n8k16.row.col.f32.bf16.bf16.f32 "
        "{%0,%1,%2,%3},{%4,%5,%6,%7},{%8,%9},{%0,%1,%2,%3};"
        : "+f"(c[0]), "+f"(c[1]), "+f"(c[2]), "+f"(c[3])
        : "r"(a[0]), "r"(a[1]), "r"(a[2]), "r"(a[3]), "r"(b[0]), "r"(b[1]));
}
__device__ __forceinline__ void ldsm_x4(uint32_t* r, uint32_t addr) {
    asm volatile("ldmatrix.sync.aligned.m8n8.x4.shared.b16 {%0,%1,%2,%3}, [%4];"
        : "=r"(r[0]), "=r"(r[1]), "=r"(r[2]), "=r"(r[3]) : "r"(addr));
}
__device__ __forceinline__ void ldsm_x4_t(uint32_t* r, uint32_t addr) {
    asm volatile("ldmatrix.sync.aligned.m8n8.x4.trans.shared.b16 {%0,%1,%2,%3}, [%4];"
        : "=r"(r[0]), "=r"(r[1]), "=r"(r[2]), "=r"(r[3]) : "r"(addr));
}
__device__ __forceinline__ void split_bf16(float x, __nv_bfloat16& h, __nv_bfloat16& l) {
    h = __float2bfloat16_rn(x);
    l = __float2bfloat16_rn(x - __bfloat162float(h));
}

__global__ void __launch_bounds__(256) qkv_gemm_tc(
    const float* __restrict__ A,
    const float* __restrict__ Wq, const float* __restrict__ Wk, const float* __restrict__ Wv)
{
    const int M = BT, N = HH, K = HH;
    const float* Bm;
    float* C;
    bool doscale = false;
    if (blockIdx.z == 0)      { Bm = Wq; C = g_q; doscale = true; }
    else if (blockIdx.z == 1) { Bm = Wk; C = g_k; }
    else                      { Bm = Wv; C = g_v; }

    __shared__ __nv_bfloat16 As[2][BM][ASTR];   // [hi/lo][m][k]
    __shared__ __nv_bfloat16 Bs[2][KT][BSTR];   // [hi/lo][k][n]

    const int tid  = threadIdx.x;
    const int lane = tid & 31;
    const int warp = tid >> 5;
    const int warp_m = (warp >> 2) * 64;   // 0 or 64
    const int warp_n = (warp & 3) * 32;    // 0..96
    const int row0 = blockIdx.y * BM;
    const int col0 = blockIdx.x * BN;

    // ldmatrix lane address components (shared by A and B patterns)
    const int lrow = ((lane >> 3) & 1) * 8 + (lane & 7);
    const int lcol = ((lane >> 4) & 1) * 8;

    const uint32_t s_as = (uint32_t)__cvta_generic_to_shared(&As[0][0][0]);
    const uint32_t s_bs = (uint32_t)__cvta_generic_to_shared(&Bs[0][0][0]);
    const uint32_t as_buf = BM * ASTR * 2;  // bytes per hi/lo buffer
    const uint32_t bs_buf = KT * BSTR * 2;

    float acc[4][4][4];
    #pragma unroll
    for (int i = 0; i < 4; i++)
        #pragma unroll
        for (int j = 0; j < 4; j++)
            #pragma unroll
            for (int r = 0; r < 4; r++) acc[i][j][r] = 0.f;

    for (int kt = 0; kt < K; kt += KT) {
        // ---- load + split A tile: 128 rows x 32 k-cols (1024 float4) ----
        #pragma unroll
        for (int it = 0; it < 4; it++) {
            int id = tid + it * 256;
            int r = id >> 3;
            int c4 = (id & 7) * 4;
            float4 v = make_float4(0.f, 0.f, 0.f, 0.f);
            if (row0 + r < M)
                v = *(const float4*)&A[(size_t)(row0 + r) * K + kt + c4];
            __nv_bfloat16 hx, lx, hy, ly, hz, lz, hw, lw;
            split_bf16(v.x, hx, lx); split_bf16(v.y, hy, ly);
            split_bf16(v.z, hz, lz); split_bf16(v.w, hw, lw);
            *(__nv_bfloat162*)&As[0][r][c4]     = __nv_bfloat162(hx, hy);
            *(__nv_bfloat162*)&As[0][r][c4 + 2] = __nv_bfloat162(hz, hw);
            *(__nv_bfloat162*)&As[1][r][c4]     = __nv_bfloat162(lx, ly);
            *(__nv_bfloat162*)&As[1][r][c4 + 2] = __nv_bfloat162(lz, lw);
        }
        // ---- load + split B tile: 32 k-rows x 128 cols (1024 float4) ----
        #pragma unroll
        for (int it = 0; it < 4; it++) {
            int id = tid + it * 256;
            int r = id >> 5;
            int c4 = (id & 31) * 4;
            float4 v = *(const float4*)&Bm[(size_t)(kt + r) * N + col0 + c4];
            if (doscale) {
                v.x *= g_colscale[col0 + c4];
                v.y *= g_colscale[col0 + c4 + 1];
                v.z *= g_colscale[col0 + c4 + 2];
                v.w *= g_colscale[col0 + c4 + 3];
            }
            __nv_bfloat16 hx, lx, hy, ly, hz, lz, hw, lw;
            split_bf16(v.x, hx, lx); split_bf16(v.y, hy, ly);
            split_bf16(v.z, hz, lz); split_bf16(v.w, hw, lw);
            *(__nv_bfloat162*)&Bs[0][r][c4]     = __nv_bfloat162(hx, hy);
            *(__nv_bfloat162*)&Bs[0][r][c4 + 2] = __nv_bfloat162(hz, hw);
            *(__nv_bfloat162*)&Bs[1][r][c4]     = __nv_bfloat162(lx, ly);
            *(__nv_bfloat162*)&Bs[1][r][c4 + 2] = __nv_bfloat162(lz, lw);
        }
        __syncthreads();

        // ---- MMA over 2 k-frags of 16 ----
        #pragma unroll
        for (int kf = 0; kf < 2; kf++) {
            // B fragments: 2 x ldmatrix.x4.trans per buffer (covers n=32)
            uint32_t bh[8], bl[8];
            #pragma unroll
            for (int nf2 = 0; nf2 < 2; nf2++) {
                uint32_t boff = ((uint32_t)(kf * 16 + lrow) * BSTR
                               + (uint32_t)(warp_n + nf2 * 16 + lcol)) * 2;
                ldsm_x4_t(&bh[nf2 * 4], s_bs + boff);
                ldsm_x4_t(&bl[nf2 * 4], s_bs + bs_buf + boff);
            }
            #pragma unroll
            for (int mf = 0; mf < 4; mf++) {
                uint32_t aoff = ((uint32_t)(warp_m + mf * 16 + lrow) * ASTR
                               + (uint32_t)(kf * 16 + lcol)) * 2;
                uint32_t ah[4], al[4];
                ldsm_x4(ah, s_as + aoff);
                ldsm_x4(al, s_as + as_buf + aoff);
                #pragma unroll
                for (int nf = 0; nf < 4; nf++) {
                    uint32_t* b_h = &bh[(nf >> 1) * 4 + (nf & 1) * 2];
                    uint32_t* b_l = &bl[(nf >> 1) * 4 + (nf & 1) * 2];
                    mma_bf16(acc[mf][nf], ah, b_h);
                    mma_bf16(acc[mf][nf], ah, b_l);
                    mma_bf16(acc[mf][nf], al, b_h);
                }
            }
        }
        __syncthreads();
    }

    // ---- epilogue ----
    const int g  = lane >> 2;
    const int t2 = (lane & 3) * 2;
    #pragma unroll
    for (int mf = 0; mf < 4; mf++) {
        int row = row0 + warp_m + mf * 16 + g;
        #pragma unroll
        for (int nf = 0; nf < 4; nf++) {
            int col = col0 + warp_n + nf * 8 + t2;
            if (row < M) {
                float2 o = make_float2(acc[mf][nf][0], acc[mf][nf][1]);
                *(float2*)&C[(size_t)row * N + col] = o;
            }
            if (row + 8 < M) {
                float2 o = make_float2(acc[mf][nf][2], acc[mf][nf][3]);
                *(float2*)&C[(size_t)(row + 8) * N + col] = o;
            }
        }
    }
}

// ---------------------------------------------------------------------------
// Attention: one block per (u, n, b). 288 threads.
// ---------------------------------------------------------------------------
#define NTHR 288
#define PADR 200

__global__ void __launch_bounds__(NTHR) attn_kernel(
    const unsigned char* __restrict__ mask, float* __restrict__ out)
{
    int u = blockIdx.x, n = blockIdx.y, b = blockIdx.z;
    int tid = threadIdx.x;

    __shared__ float sq[CHUNK][PADR];
    __shared__ float skv[CTXS][PADR];
    __shared__ float sp[FSPAN][PADR];
    __shared__ float sbd[CHUNK][16];
    __shared__ float sprob[CHUNK][CTXS];
    __shared__ unsigned char svalid[CTXS];

    const size_t headoff = (size_t)n * HD;
    const size_t qbase = ((size_t)b * TT + (size_t)u * CHUNK) * HH + headoff;

    for (int i = tid; i < CHUNK * HD; i += NTHR) {
        int w = i / HD, d = i % HD;
        sq[w][d] = g_q[qbase + (size_t)w * HH + d];
    }
    for (int i = tid; i < CTXS * HD; i += NTHR) {
        int c = i / HD, d = i % HD;
        int pos = u * CHUNK + c - PAST;
        float val = 0.f;
        if (pos >= 0 && pos < TT)
            val = g_k[((size_t)b * TT + pos) * HH + headoff + d];
        skv[c][d] = val;
    }
    for (int i = tid; i < FSPAN * HD; i += NTHR) {
        int f = i / HD, d = i % HD;
        sp[f][d] = g_sinproj[f * HH + headoff + d];
    }
    if (tid < CTXS) {
        int pos = u * CHUNK + tid - PAST;
        svalid[tid] = (pos >= 0 && pos < TT) ? (mask[(size_t)b * TT + pos] ? 0 : 1) : 0;
    }
    __syncthreads();

    for (int i = tid; i < CHUNK * FSPAN; i += NTHR) {
        int w = i / FSPAN, f = i % FSPAN;
        float acc = 0.f;
        #pragma unroll 8
        for (int d = 0; d < HD; d++) acc = fmaf(sq[w][d], sp[f][d], acc);
        sbd[w][f] = acc;
    }
    __syncthreads();

    {
        int w = tid / CTXS, c = tid % CTXS;  // tid < 288 == 12*24
        float acc = 0.f;
        #pragma unroll 8
        for (int d = 0; d < HD; d++) acc = fmaf(sq[w][d], skv[c][d], acc);
        int f = c - w;
        bool band = (f >= 0 && f <= PAST);
        if (band) acc += sbd[w][f];
        acc = tanhf(acc * 0.02f) * 50.f;
        bool ok = band && svalid[c];
        sprob[w][c] = ok ? acc : -1e30f;
    }
    __syncthreads();

    if (tid < CHUNK) {
        float m = -1e30f;
        #pragma unroll
        for (int c = 0; c < CTXS; c++) m = fmaxf(m, sprob[tid][c]);
        float e[CTXS];
        float s = 0.f;
        #pragma unroll
        for (int c = 0; c < CTXS; c++) { e[c] = __expf(sprob[tid][c] - m); s += e[c]; }
        float inv = 1.f / s;
        #pragma unroll
        for (int c = 0; c < CTXS; c++) sprob[tid][c] = e[c] * inv;
    }
    __syncthreads();

    for (int i = tid; i < CTXS * HD; i += NTHR) {
        int c = i / HD, d = i % HD;
        int pos = u * CHUNK + c - PAST;
        float val = 0.f;
        if (pos >= 0 && pos < TT)
            val = g_v[((size_t)b * TT + pos) * HH + headoff + d];
        skv[c][d] = val;
    }
    __syncthreads();

    for (int i = tid; i < CHUNK * HD; i += NTHR) {
        int w = i / HD, d = i % HD;
        float acc = 0.f;
        #pragma unroll
        for (int c = 0; c < CTXS; c++) acc = fmaf(sprob[w][c], skv[c][d], acc);
        out[qbase + (size_t)w * HH + d] = acc;
    }
}

// ---------------------------------------------------------------------------
extern "C" void kernel_launch(void* const* d_in, const int* in_sizes, int n_in,
                              void* d_out, int out_size) {
    const float* hs   = (const float*)d_in[0];
    const float* Wq   = (const float*)d_in[1];
    const float* Wk   = (const float*)d_in[2];
    const float* Wv   = (const float*)d_in[3];
    const float* Wpos = (const float*)d_in[4];
    const float* ps   = (const float*)d_in[5];
    const unsigned char* mask = (const unsigned char*)d_in[6];
    float* out = (float*)d_out;

    colscale_kernel<<<(HH + 255) / 256, 256>>>(ps);
    sinproj_kernel<<<dim3(FSPAN, HH / 128), 128>>>(Wpos);

    dim3 ggrid(HH / BN, (BT + BM - 1) / BM, 3);
    qkv_gemm_tc<<<ggrid, 256>>>(hs, Wq, Wk, Wv);

    attn_kernel<<<dim3(UU, NHD, BB), NTHR>>>(mask, out);
}